// round 12
// baseline (speedup 1.0000x reference)
#include <cuda_runtime.h>
#include <cuda_bf16.h>
#include <stdint.h>

#define D 1024
#define HEADS 16
#define KP 3072            // split-K' = 3 x 1024
#define LDAB 40            // gemm smem row stride in bf16
#define NSTAGE 3
#define STAGE_BYTES 20480
#define GSMEM (NSTAGE * STAGE_BYTES)

#define ATT_T 72                       // attn smem row stride (halves)
#define ATT_MAT_B (64 * ATT_T * 2)     // 9216 bytes per 64x64 bf16 matrix
#define ATT_SMEM (2 * ATT_MAT_B + 2 * 4 * ATT_MAT_B)  // 92160

// ---------------- scratch (allocation-free rule) ----------------
__device__ __align__(16) __nv_bfloat16 g_Qhi[4096 * 1024];
__device__ __align__(16) __nv_bfloat16 g_Qlo[4096 * 1024];
__device__ __align__(16) __nv_bfloat16 g_Khi[4096 * 1024];
__device__ __align__(16) __nv_bfloat16 g_Klo[4096 * 1024];
__device__ __align__(16) __nv_bfloat16 g_Vhi[4096 * 1024];
__device__ __align__(16) __nv_bfloat16 g_Vlo[4096 * 1024];
__device__ __align__(16) __nv_bfloat16 g_Aq[4096 * KP];
__device__ __align__(16) __nv_bfloat16 g_Ak[4096 * KP];
__device__ __align__(16) __nv_bfloat16 g_Av[4096 * KP];
__device__ __align__(16) __nv_bfloat16 g_Ac[4096 * KP];
__device__ __align__(16) __nv_bfloat16 g_Wq2[1024 * KP];
__device__ __align__(16) __nv_bfloat16 g_Wk2[1024 * KP];
__device__ __align__(16) __nv_bfloat16 g_Wv2[1024 * KP];
__device__ __align__(16) __nv_bfloat16 g_Wo2[1024 * KP];

// ---------------- PTX helpers ----------------
__device__ __forceinline__ uint32_t smem_u32(const void* p) {
    uint32_t a;
    asm("{ .reg .u64 t; cvta.to.shared.u64 t, %1; cvt.u32.u64 %0, t; }" : "=r"(a) : "l"(p));
    return a;
}
__device__ __forceinline__ void cp16(uint32_t dst, const void* src) {
    asm volatile("cp.async.cg.shared.global [%0], [%1], 16;\n" :: "r"(dst), "l"(src) : "memory");
}
#define CP_COMMIT() asm volatile("cp.async.commit_group;\n" ::: "memory")
#define CP_WAIT(n) asm volatile("cp.async.wait_group %0;\n" :: "n"(n) : "memory")

__device__ __forceinline__ void ldsm_x4(uint32_t& r0, uint32_t& r1, uint32_t& r2, uint32_t& r3, uint32_t addr) {
    asm volatile("ldmatrix.sync.aligned.m8n8.x4.shared.b16 {%0,%1,%2,%3}, [%4];"
                 : "=r"(r0), "=r"(r1), "=r"(r2), "=r"(r3) : "r"(addr));
}
__device__ __forceinline__ void ldsm_x4_t(uint32_t& r0, uint32_t& r1, uint32_t& r2, uint32_t& r3, uint32_t addr) {
    asm volatile("ldmatrix.sync.aligned.m8n8.x4.trans.shared.b16 {%0,%1,%2,%3}, [%4];"
                 : "=r"(r0), "=r"(r1), "=r"(r2), "=r"(r3) : "r"(addr));
}
__device__ __forceinline__ void mma_bf16(float* c, uint32_t a0, uint32_t a1, uint32_t a2, uint32_t a3,
                                         uint32_t b0, uint32_t b1) {
    asm volatile(
        "mma.sync.aligned.m16n8k16.row.col.f32.bf16.bf16.f32 "
        "{%0,%1,%2,%3}, {%4,%5,%6,%7}, {%8,%9}, {%0,%1,%2,%3};"
        : "+f"(c[0]), "+f"(c[1]), "+f"(c[2]), "+f"(c[3])
        : "r"(a0), "r"(a1), "r"(a2), "r"(a3), "r"(b0), "r"(b1));
}

// ---------------- fp32 -> bf16 hi/lo 3-segment split ----------------
union B4 { __nv_bfloat162 h2[2]; uint2 u; };

__device__ __forceinline__ void split_one(const float* __restrict__ x,
                                          __nv_bfloat16* __restrict__ out,
                                          int i, int mode) {
    float4 v = *(const float4*)(x + i);
    __nv_bfloat16 h0 = __float2bfloat16(v.x), h1 = __float2bfloat16(v.y);
    __nv_bfloat16 h2 = __float2bfloat16(v.z), h3 = __float2bfloat16(v.w);
    __nv_bfloat16 l0 = __float2bfloat16(v.x - __bfloat162float(h0));
    __nv_bfloat16 l1 = __float2bfloat16(v.y - __bfloat162float(h1));
    __nv_bfloat16 l2 = __float2bfloat16(v.z - __bfloat162float(h2));
    __nv_bfloat16 l3 = __float2bfloat16(v.w - __bfloat162float(h3));
    B4 hv, lv;
    hv.h2[0] = __nv_bfloat162(h0, h1); hv.h2[1] = __nv_bfloat162(h2, h3);
    lv.h2[0] = __nv_bfloat162(l0, l1); lv.h2[1] = __nv_bfloat162(l2, l3);
    int row = i >> 10, col = i & 1023;
    size_t base = (size_t)row * KP + col;
    *(uint2*)(out + base) = hv.u;
    if (mode == 0) {
        *(uint2*)(out + base + 1024) = hv.u;
        *(uint2*)(out + base + 2048) = lv.u;
    } else {
        *(uint2*)(out + base + 1024) = lv.u;
        *(uint2*)(out + base + 2048) = hv.u;
    }
}

__global__ __launch_bounds__(256) void split_all(
    const float* __restrict__ q, const float* __restrict__ k, const float* __restrict__ v,
    const float* __restrict__ wq, const float* __restrict__ wk,
    const float* __restrict__ wv, const float* __restrict__ wo,
    __nv_bfloat16* __restrict__ oq, __nv_bfloat16* __restrict__ ok, __nv_bfloat16* __restrict__ ov,
    __nv_bfloat16* __restrict__ owq, __nv_bfloat16* __restrict__ owk,
    __nv_bfloat16* __restrict__ owv, __nv_bfloat16* __restrict__ owo) {
    int bid = blockIdx.x;
    const float* src;
    __nv_bfloat16* dst;
    int mode, lb;
    if (bid < 12288) {
        int t = bid >> 12;
        lb = bid & 4095;
        src = (t == 0) ? q : (t == 1) ? k : v;
        dst = (t == 0) ? oq : (t == 1) ? ok : ov;
        mode = 0;
    } else {
        int t = (bid - 12288) >> 10;
        lb = (bid - 12288) & 1023;
        src = (t == 0) ? wq : (t == 1) ? wk : (t == 2) ? wv : wo;
        dst = (t == 0) ? owq : (t == 1) ? owk : (t == 2) ? owv : owo;
        mode = 1;
    }
    int i = (lb * 256 + threadIdx.x) * 4;
    split_one(src, dst, i, mode);
}

// ---------------- bf16 mma.sync GEMM: 128x128 CTA tile, 4 warps of 64x64 ----------------
// 128 threads, 2 CTAs/SM, BK=32, 3-stage cp.async pipeline, register double-buffered frags.
struct Frags {
    uint32_t a[4][4];
    uint32_t b[8][2];
};

__device__ __forceinline__ void load_stage(uint32_t sm, const __nv_bfloat16* A,
                                           const __nv_bfloat16* B, int bm, int bn,
                                           int it, int tid) {
    size_t kof = (size_t)it * 32;
#pragma unroll
    for (int i = 0; i < 4; i++) {
        int c = tid + 128 * i;
        int r = c >> 2, kc = (c & 3) * 8;
        cp16(sm + (r * LDAB + kc) * 2, A + (size_t)(bm + r) * KP + kof + kc);
    }
#pragma unroll
    for (int i = 0; i < 4; i++) {
        int c = tid + 128 * i;
        int r = c >> 2, kc = (c & 3) * 8;
        cp16(sm + 10240 + (r * LDAB + kc) * 2, B + (size_t)(bn + r) * KP + kof + kc);
    }
}

__global__ __launch_bounds__(128, 2) void gemm_mma(
    const __nv_bfloat16* __restrict__ A, const __nv_bfloat16* __restrict__ W,
    const float* __restrict__ bias, float* __restrict__ C,
    __nv_bfloat16* __restrict__ Chi, __nv_bfloat16* __restrict__ Clo) {
    extern __shared__ char smem[];
    const uint32_t sb = smem_u32(smem);
    const int tid = threadIdx.x;
    const int wid = tid >> 5;
    const int l = tid & 31;
    const int warp_m = wid >> 1;   // 0..1
    const int warp_n = wid & 1;    // 0..1
    const int bm = blockIdx.y * 128;
    const int bn = blockIdx.x * 128;
    const int NIT = KP / 32;       // 96

    float acc[4][8][4];
#pragma unroll
    for (int mi = 0; mi < 4; mi++)
#pragma unroll
        for (int ni = 0; ni < 8; ni++)
#pragma unroll
            for (int r = 0; r < 4; r++) acc[mi][ni][r] = 0.0f;

    const int a_row = warp_m * 64 + (l & 15);
    const int a_ko = (l >> 4) << 3;
    const int b_row = warp_n * 64 + ((l >> 4) << 3) + (l & 7);
    const int b_ko = ((l >> 3) & 1) << 3;

    auto ldsm_frags = [&](Frags& f, uint32_t stage, int kcol) {
#pragma unroll
        for (int mi = 0; mi < 4; mi++)
            ldsm_x4(f.a[mi][0], f.a[mi][1], f.a[mi][2], f.a[mi][3],
                    stage + ((a_row + mi * 16) * LDAB + kcol + a_ko) * 2);
#pragma unroll
        for (int p = 0; p < 4; p++) {
            uint32_t r0, r1, r2, r3;
            ldsm_x4(r0, r1, r2, r3,
                    stage + 10240 + ((b_row + p * 16) * LDAB + kcol + b_ko) * 2);
            f.b[2 * p][0] = r0; f.b[2 * p][1] = r1;
            f.b[2 * p + 1][0] = r2; f.b[2 * p + 1][1] = r3;
        }
    };
    auto mma_all = [&](const Frags& f) {
#pragma unroll
        for (int mi = 0; mi < 4; mi++)
#pragma unroll
            for (int ni = 0; ni < 8; ni++)
                mma_bf16(acc[mi][ni], f.a[mi][0], f.a[mi][1], f.a[mi][2], f.a[mi][3],
                         f.b[ni][0], f.b[ni][1]);
    };

#pragma unroll
    for (int s = 0; s < NSTAGE - 1; s++) {
        load_stage(sb + s * STAGE_BYTES, A, W, bm, bn, s, tid);
        CP_COMMIT();
    }
    CP_WAIT(1);
    __syncthreads();

    Frags cur, nxt;
    ldsm_frags(cur, sb, 0);

    for (int it = 0; it < NIT; it++) {
        const uint32_t sCur = sb + (it % NSTAGE) * STAGE_BYTES;
        if (it + 2 < NIT)
            load_stage(sb + ((it + 2) % NSTAGE) * STAGE_BYTES, A, W, bm, bn, it + 2, tid);
        CP_COMMIT();

        ldsm_frags(nxt, sCur, 16);
        mma_all(cur);

        if (it + 1 < NIT) {
            CP_WAIT(1);
            __syncthreads();
            ldsm_frags(cur, sb + ((it + 1) % NSTAGE) * STAGE_BYTES, 0);
        }
        mma_all(nxt);
    }

    const int tr = l >> 2;
    const int tc = (l & 3) * 2;
#pragma unroll
    for (int mi = 0; mi < 4; mi++) {
#pragma unroll
        for (int ni = 0; ni < 8; ni++) {
            int row0 = bm + warp_m * 64 + mi * 16 + tr;
            int col = bn + warp_n * 64 + ni * 8 + tc;
            float2 v0 = make_float2(acc[mi][ni][0], acc[mi][ni][1]);
            float2 v1 = make_float2(acc[mi][ni][2], acc[mi][ni][3]);
            if (bias) {
                float2 bv = *(const float2*)(bias + col);
                v0.x += bv.x; v0.y += bv.y;
                v1.x += bv.x; v1.y += bv.y;
            }
            if (C) {
                *(float2*)(C + (size_t)row0 * 1024 + col) = v0;
                *(float2*)(C + (size_t)(row0 + 8) * 1024 + col) = v1;
            }
            if (Chi) {
                __nv_bfloat16 h0 = __float2bfloat16(v0.x), h1 = __float2bfloat16(v0.y);
                __nv_bfloat16 h2 = __float2bfloat16(v1.x), h3 = __float2bfloat16(v1.y);
                __nv_bfloat162 hp0(h0, h1), hp1(h2, h3);
                __nv_bfloat162 lp0(__float2bfloat16(v0.x - __bfloat162float(h0)),
                                   __float2bfloat16(v0.y - __bfloat162float(h1)));
                __nv_bfloat162 lp1(__float2bfloat16(v1.x - __bfloat162float(h2)),
                                   __float2bfloat16(v1.y - __bfloat162float(h3)));
                *(uint32_t*)(Chi + (size_t)row0 * 1024 + col) = *(uint32_t*)&hp0;
                *(uint32_t*)(Chi + (size_t)(row0 + 8) * 1024 + col) = *(uint32_t*)&hp1;
                *(uint32_t*)(Clo + (size_t)row0 * 1024 + col) = *(uint32_t*)&lp0;
                *(uint32_t*)(Clo + (size_t)(row0 + 8) * 1024 + col) = *(uint32_t*)&lp1;
            }
        }
    }
}

// ---------------- tensor-core flash attention ----------------
// Epilogue now writes Ac (split-K' mode-0 layout) directly: ctx fp32 + split3 fused away.
__global__ __launch_bounds__(128) void attn_tc(
    const __nv_bfloat16* __restrict__ Qhi, const __nv_bfloat16* __restrict__ Qlo,
    const __nv_bfloat16* __restrict__ Khi, const __nv_bfloat16* __restrict__ Klo,
    const __nv_bfloat16* __restrict__ Vhi, const __nv_bfloat16* __restrict__ Vlo,
    __nv_bfloat16* __restrict__ Ac, int S) {
    extern __shared__ char smem[];
    const uint32_t sb = smem_u32(smem);
    const int tid = threadIdx.x;
    const int w = tid >> 5;
    const int l = tid & 31;
    const int tr = l >> 2;
    const int tc = l & 3;
    const int qt = blockIdx.x, h = blockIdx.y, b = blockIdx.z;
    const int NT = S / 64;

    const uint32_t oQhi = sb;
    const uint32_t oQlo = sb + ATT_MAT_B;
    const uint32_t oSt = sb + 2 * ATT_MAT_B;

    const size_t gq = ((size_t)(b * S + qt * 64)) * D + (size_t)h * 64;

#pragma unroll
    for (int i = 0; i < 8; i++) {
        int c = tid + 128 * i;
        int mat = c >> 9, r = (c >> 3) & 63, cc = c & 7;
        const __nv_bfloat16* src = mat ? Qlo : Qhi;
        cp16((mat ? oQlo : oQhi) + (r * ATT_T + cc * 8) * 2, src + gq + (size_t)r * D + cc * 8);
    }
    auto load_kv = [&](int stage, int kt) {
        size_t gk = ((size_t)(b * S + kt * 64)) * D + (size_t)h * 64;
        const __nv_bfloat16* mats[4] = {Khi, Klo, Vhi, Vlo};
#pragma unroll
        for (int i = 0; i < 16; i++) {
            int c = tid + 128 * i;
            int mat = c >> 9, r = (c >> 3) & 63, cc = c & 7;
            cp16(oSt + stage * (4 * ATT_MAT_B) + mat * ATT_MAT_B + (r * ATT_T + cc * 8) * 2,
                 mats[mat] + gk + (size_t)r * D + cc * 8);
        }
    };
    load_kv(0, 0);
    CP_COMMIT();
    load_kv(1, 1);
    CP_COMMIT();
    CP_WAIT(1);
    __syncthreads();

    uint32_t qh[4][4], ql[4][4];
    {
        const int arow = w * 16 + (l & 15);
        const int ako = (l >> 4) << 3;
#pragma unroll
        for (int kk = 0; kk < 4; kk++) {
            ldsm_x4(qh[kk][0], qh[kk][1], qh[kk][2], qh[kk][3],
                    oQhi + (arow * ATT_T + kk * 16 + ako) * 2);
            ldsm_x4(ql[kk][0], ql[kk][1], ql[kk][2], ql[kk][3],
                    oQlo + (arow * ATT_T + kk * 16 + ako) * 2);
        }
    }

    float oacc[8][4];
#pragma unroll
    for (int ni = 0; ni < 8; ni++)
#pragma unroll
        for (int j = 0; j < 4; j++) oacc[ni][j] = 0.0f;
    float m0 = -1e30f, m1 = -1e30f, sl0 = 0.0f, sl1 = 0.0f;

    const int brow = ((l >> 4) << 3) + (l & 7);
    const int bko = ((l >> 3) & 1) << 3;
    const int vrow = (l & 7) + (((l >> 3) & 1) << 3);
    const int vcolw = (l >> 4);

    for (int kt = 0; kt < NT; kt++) {
        const uint32_t KBh = oSt + (kt & 1) * (4 * ATT_MAT_B);
        const uint32_t KBl = KBh + ATT_MAT_B;
        const uint32_t VBh = KBh + 2 * ATT_MAT_B;
        const uint32_t VBl = KBh + 3 * ATT_MAT_B;

        float sacc[8][4];
#pragma unroll
        for (int ni = 0; ni < 8; ni++)
#pragma unroll
            for (int j = 0; j < 4; j++) sacc[ni][j] = 0.0f;

#pragma unroll
        for (int kk = 0; kk < 4; kk++) {
            uint32_t bh[8][2];
#pragma unroll
            for (int np = 0; np < 4; np++) {
                uint32_t r0, r1, r2, r3;
                ldsm_x4(r0, r1, r2, r3, KBh + ((np * 16 + brow) * ATT_T + kk * 16 + bko) * 2);
                bh[2 * np][0] = r0; bh[2 * np][1] = r1;
                bh[2 * np + 1][0] = r2; bh[2 * np + 1][1] = r3;
            }
#pragma unroll
            for (int ni = 0; ni < 8; ni++)
                mma_bf16(sacc[ni], qh[kk][0], qh[kk][1], qh[kk][2], qh[kk][3], bh[ni][0], bh[ni][1]);
#pragma unroll
            for (int ni = 0; ni < 8; ni++)
                mma_bf16(sacc[ni], ql[kk][0], ql[kk][1], ql[kk][2], ql[kk][3], bh[ni][0], bh[ni][1]);
            uint32_t bl[8][2];
#pragma unroll
            for (int np = 0; np < 4; np++) {
                uint32_t r0, r1, r2, r3;
                ldsm_x4(r0, r1, r2, r3, KBl + ((np * 16 + brow) * ATT_T + kk * 16 + bko) * 2);
                bl[2 * np][0] = r0; bl[2 * np][1] = r1;
                bl[2 * np + 1][0] = r2; bl[2 * np + 1][1] = r3;
            }
#pragma unroll
            for (int ni = 0; ni < 8; ni++)
                mma_bf16(sacc[ni], qh[kk][0], qh[kk][1], qh[kk][2], qh[kk][3], bl[ni][0], bl[ni][1]);
        }

        float mx0 = -1e30f, mx1 = -1e30f;
#pragma unroll
        for (int ni = 0; ni < 8; ni++) {
            sacc[ni][0] *= 0.125f; sacc[ni][1] *= 0.125f;
            sacc[ni][2] *= 0.125f; sacc[ni][3] *= 0.125f;
            mx0 = fmaxf(mx0, fmaxf(sacc[ni][0], sacc[ni][1]));
            mx1 = fmaxf(mx1, fmaxf(sacc[ni][2], sacc[ni][3]));
        }
        mx0 = fmaxf(mx0, __shfl_xor_sync(0xffffffffu, mx0, 1));
        mx0 = fmaxf(mx0, __shfl_xor_sync(0xffffffffu, mx0, 2));
        mx1 = fmaxf(mx1, __shfl_xor_sync(0xffffffffu, mx1, 1));
        mx1 = fmaxf(mx1, __shfl_xor_sync(0xffffffffu, mx1, 2));
        float mn0 = fmaxf(m0, mx0), mn1 = fmaxf(m1, mx1);
        float c0 = __expf(m0 - mn0), c1 = __expf(m1 - mn1);
        float rs0 = 0.0f, rs1 = 0.0f;
#pragma unroll
        for (int ni = 0; ni < 8; ni++) {
            sacc[ni][0] = __expf(sacc[ni][0] - mn0);
            sacc[ni][1] = __expf(sacc[ni][1] - mn0);
            sacc[ni][2] = __expf(sacc[ni][2] - mn1);
            sacc[ni][3] = __expf(sacc[ni][3] - mn1);
            rs0 += sacc[ni][0] + sacc[ni][1];
            rs1 += sacc[ni][2] + sacc[ni][3];
        }
        rs0 += __shfl_xor_sync(0xffffffffu, rs0, 1);
        rs0 += __shfl_xor_sync(0xffffffffu, rs0, 2);
        rs1 += __shfl_xor_sync(0xffffffffu, rs1, 1);
        rs1 += __shfl_xor_sync(0xffffffffu, rs1, 2);
        sl0 = sl0 * c0 + rs0;
        sl1 = sl1 * c1 + rs1;
        m0 = mn0; m1 = mn1;
#pragma unroll
        for (int ni = 0; ni < 8; ni++) {
            oacc[ni][0] *= c0; oacc[ni][1] *= c0;
            oacc[ni][2] *= c1; oacc[ni][3] *= c1;
        }

        uint32_t ph[4][4], pl[4][4];
#pragma unroll
        for (int kk = 0; kk < 4; kk++) {
#pragma unroll
            for (int hv = 0; hv < 2; hv++) {
#pragma unroll
                for (int half = 0; half < 2; half++) {
                    float x = sacc[2 * kk + half][2 * hv + 0];
                    float y = sacc[2 * kk + half][2 * hv + 1];
                    __nv_bfloat16 hx = __float2bfloat16(x), hy = __float2bfloat16(y);
                    __nv_bfloat162 hp(hx, hy);
                    __nv_bfloat162 lp(__float2bfloat16(x - __bfloat162float(hx)),
                                      __float2bfloat16(y - __bfloat162float(hy)));
                    ph[kk][half * 2 + hv] = *(uint32_t*)&hp;
                    pl[kk][half * 2 + hv] = *(uint32_t*)&lp;
                }
            }
        }

#pragma unroll
        for (int kk = 0; kk < 4; kk++) {
            uint32_t bv[8][2];
#pragma unroll
            for (int np = 0; np < 4; np++) {
                uint32_t r0, r1, r2, r3;
                ldsm_x4_t(r0, r1, r2, r3,
                          VBh + ((kk * 16 + vrow) * ATT_T + 8 * (2 * np + vcolw)) * 2);
                bv[2 * np][0] = r0; bv[2 * np][1] = r1;
                bv[2 * np + 1][0] = r2; bv[2 * np + 1][1] = r3;
            }
#pragma unroll
            for (int ni = 0; ni < 8; ni++)
                mma_bf16(oacc[ni], ph[kk][0], ph[kk][1], ph[kk][2], ph[kk][3], bv[ni][0], bv[ni][1]);
#pragma unroll
            for (int ni = 0; ni < 8; ni++)
                mma_bf16(oacc[ni], pl[kk][0], pl[kk][1], pl[kk][2], pl[kk][3], bv[ni][0], bv[ni][1]);
            uint32_t bvl[8][2];
#pragma unroll
            for (int np = 0; np < 4; np++) {
                uint32_t r0, r1, r2, r3;
                ldsm_x4_t(r0, r1, r2, r3,
                          VBl + ((kk * 16 + vrow) * ATT_T + 8 * (2 * np + vcolw)) * 2);
                bvl[2 * np][0] = r0; bvl[2 * np][1] = r1;
                bvl[2 * np + 1][0] = r2; bvl[2 * np + 1][1] = r3;
            }
#pragma unroll
            for (int ni = 0; ni < 8; ni++)
                mma_bf16(oacc[ni], ph[kk][0], ph[kk][1], ph[kk][2], ph[kk][3], bvl[ni][0], bvl[ni][1]);
        }

        __syncthreads();
        if (kt + 2 < NT) {
            load_kv(kt & 1, kt + 2);
            CP_COMMIT();
            CP_WAIT(1);
            __syncthreads();
        } else if (kt + 1 < NT) {
            CP_WAIT(0);
            __syncthreads();
        }
    }

    // ---- epilogue: write Ac hi/lo in split-K' mode-0 layout directly ----
    float i0 = 1.0f / sl0, i1 = 1.0f / sl1;
    const int qrow = qt * 64 + w * 16;
    auto store_pair = [&](int grow, int col, float x, float y) {
        __nv_bfloat16 hx = __float2bfloat16(x), hy = __float2bfloat16(y);
        __nv_bfloat162 hp(hx, hy);
        __nv_bfloat162 lp(__float2bfloat16(x - __bfloat162float(hx)),
                          __float2bfloat16(y - __bfloat162float(hy)));
        size_t base = (size_t)grow * KP + col;
        *(uint32_t*)(Ac + base) = *(uint32_t*)&hp;
        *(uint32_t*)(Ac + base + 1024) = *(uint32_t*)&hp;
        *(uint32_t*)(Ac + base + 2048) = *(uint32_t*)&lp;
    };
#pragma unroll
    for (int ni = 0; ni < 8; ni++) {
        int grow = b * S + qrow + tr;
        int col = h * 64 + ni * 8 + tc * 2;
        store_pair(grow, col, oacc[ni][0] * i0, oacc[ni][1] * i0);
        store_pair(grow + 8, col, oacc[ni][2] * i1, oacc[ni][3] * i1);
    }
}

// ---------------- launch ----------------
extern "C" void kernel_launch(void* const* d_in, const int* in_sizes, int n_in,
                              void* d_out, int out_size) {
    const float* key = (const float*)d_in[0];
    const float* query = (const float*)d_in[1];
    const float* value = (const float*)d_in[2];
    const float* Wq = (const float*)d_in[3];
    const float* Wk = (const float*)d_in[4];
    const float* Wv = (const float*)d_in[5];
    const float* Wo = (const float*)d_in[6];
    const float* bo = (const float*)d_in[7];

    const int B = 2;
    const int S = in_sizes[0] / (B * D);  // 2048
    const int M = B * S;                  // 4096

    __nv_bfloat16 *Aq, *Ak, *Av, *Ac, *Wq2, *Wk2, *Wv2, *Wo2;
    __nv_bfloat16 *Qh, *Ql, *Kh, *Kl, *Vh, *Vl;
    cudaGetSymbolAddress((void**)&Aq, g_Aq);
    cudaGetSymbolAddress((void**)&Ak, g_Ak);
    cudaGetSymbolAddress((void**)&Av, g_Av);
    cudaGetSymbolAddress((void**)&Ac, g_Ac);
    cudaGetSymbolAddress((void**)&Wq2, g_Wq2);
    cudaGetSymbolAddress((void**)&Wk2, g_Wk2);
    cudaGetSymbolAddress((void**)&Wv2, g_Wv2);
    cudaGetSymbolAddress((void**)&Wo2, g_Wo2);
    cudaGetSymbolAddress((void**)&Qh, g_Qhi);
    cudaGetSymbolAddress((void**)&Ql, g_Qlo);
    cudaGetSymbolAddress((void**)&Kh, g_Khi);
    cudaGetSymbolAddress((void**)&Kl, g_Klo);
    cudaGetSymbolAddress((void**)&Vh, g_Vhi);
    cudaGetSymbolAddress((void**)&Vl, g_Vlo);

    cudaFuncSetAttribute(gemm_mma, cudaFuncAttributeMaxDynamicSharedMemorySize, GSMEM);
    cudaFuncSetAttribute(attn_tc, cudaFuncAttributeMaxDynamicSharedMemorySize, ATT_SMEM);

    dim3 gG(D / 128, M / 128);  // (8, 32)

    split_all<<<16384, 256>>>(query, key, value, Wq, Wk, Wv, Wo,
                              Aq, Ak, Av, Wq2, Wk2, Wv2, Wo2);
    gemm_mma<<<gG, 128, GSMEM>>>(Aq, Wq2, nullptr, nullptr, Qh, Ql);
    gemm_mma<<<gG, 128, GSMEM>>>(Ak, Wk2, nullptr, nullptr, Kh, Kl);
    gemm_mma<<<gG, 128, GSMEM>>>(Av, Wv2, nullptr, nullptr, Vh, Vl);

    dim3 gAt(S / 64, HEADS, B);  // (32, 16, 2)
    attn_tc<<<gAt, 128, ATT_SMEM>>>(Qh, Ql, Kh, Kl, Vh, Vl, Ac, S);

    gemm_mma<<<gG, 128, GSMEM>>>(Ac, Wo2, bo, (float*)d_out, nullptr, nullptr);
}

// round 13
// speedup vs baseline: 1.0391x; 1.0391x over previous
#include <cuda_runtime.h>
#include <cuda_bf16.h>
#include <stdint.h>

#define D 1024
#define HEADS 16
#define KP 3072            // split-K' = 3 x 1024
#define LDAB 40            // gemm smem row stride in bf16
#define NSTAGE 4
#define STAGE_BYTES 20480
#define GSMEM (NSTAGE * STAGE_BYTES)   // 81920; 2 CTAs/SM = 160KB <= 228KB

#define ATT_T 72                       // attn smem row stride (halves)
#define ATT_MAT_B (64 * ATT_T * 2)     // 9216 bytes per 64x64 bf16 matrix
#define ATT_SMEM (2 * ATT_MAT_B + 2 * 4 * ATT_MAT_B)  // 92160

// ---------------- scratch (allocation-free rule) ----------------
__device__ __align__(16) __nv_bfloat16 g_Qhi[4096 * 1024];
__device__ __align__(16) __nv_bfloat16 g_Qlo[4096 * 1024];
__device__ __align__(16) __nv_bfloat16 g_Khi[4096 * 1024];
__device__ __align__(16) __nv_bfloat16 g_Klo[4096 * 1024];
__device__ __align__(16) __nv_bfloat16 g_Vhi[4096 * 1024];
__device__ __align__(16) __nv_bfloat16 g_Vlo[4096 * 1024];
__device__ __align__(16) __nv_bfloat16 g_Aq[4096 * KP];
__device__ __align__(16) __nv_bfloat16 g_Ak[4096 * KP];
__device__ __align__(16) __nv_bfloat16 g_Av[4096 * KP];
__device__ __align__(16) __nv_bfloat16 g_Ac[4096 * KP];
__device__ __align__(16) __nv_bfloat16 g_Wq2[1024 * KP];
__device__ __align__(16) __nv_bfloat16 g_Wk2[1024 * KP];
__device__ __align__(16) __nv_bfloat16 g_Wv2[1024 * KP];
__device__ __align__(16) __nv_bfloat16 g_Wo2[1024 * KP];

// ---------------- PTX helpers ----------------
__device__ __forceinline__ uint32_t smem_u32(const void* p) {
    uint32_t a;
    asm("{ .reg .u64 t; cvta.to.shared.u64 t, %1; cvt.u32.u64 %0, t; }" : "=r"(a) : "l"(p));
    return a;
}
__device__ __forceinline__ void cp16(uint32_t dst, const void* src) {
    asm volatile("cp.async.cg.shared.global [%0], [%1], 16;\n" :: "r"(dst), "l"(src) : "memory");
}
#define CP_COMMIT() asm volatile("cp.async.commit_group;\n" ::: "memory")
#define CP_WAIT(n) asm volatile("cp.async.wait_group %0;\n" :: "n"(n) : "memory")

__device__ __forceinline__ void ldsm_x4(uint32_t& r0, uint32_t& r1, uint32_t& r2, uint32_t& r3, uint32_t addr) {
    asm volatile("ldmatrix.sync.aligned.m8n8.x4.shared.b16 {%0,%1,%2,%3}, [%4];"
                 : "=r"(r0), "=r"(r1), "=r"(r2), "=r"(r3) : "r"(addr));
}
__device__ __forceinline__ void ldsm_x4_t(uint32_t& r0, uint32_t& r1, uint32_t& r2, uint32_t& r3, uint32_t addr) {
    asm volatile("ldmatrix.sync.aligned.m8n8.x4.trans.shared.b16 {%0,%1,%2,%3}, [%4];"
                 : "=r"(r0), "=r"(r1), "=r"(r2), "=r"(r3) : "r"(addr));
}
__device__ __forceinline__ void mma_bf16(float* c, uint32_t a0, uint32_t a1, uint32_t a2, uint32_t a3,
                                         uint32_t b0, uint32_t b1) {
    asm volatile(
        "mma.sync.aligned.m16n8k16.row.col.f32.bf16.bf16.f32 "
        "{%0,%1,%2,%3}, {%4,%5,%6,%7}, {%8,%9}, {%0,%1,%2,%3};"
        : "+f"(c[0]), "+f"(c[1]), "+f"(c[2]), "+f"(c[3])
        : "r"(a0), "r"(a1), "r"(a2), "r"(a3), "r"(b0), "r"(b1));
}

// ---------------- fp32 -> bf16 hi/lo 3-segment split ----------------
union B4 { __nv_bfloat162 h2[2]; uint2 u; };

__device__ __forceinline__ void split_one(const float* __restrict__ x,
                                          __nv_bfloat16* __restrict__ out,
                                          int i, int mode) {
    float4 v = *(const float4*)(x + i);
    __nv_bfloat16 h0 = __float2bfloat16(v.x), h1 = __float2bfloat16(v.y);
    __nv_bfloat16 h2 = __float2bfloat16(v.z), h3 = __float2bfloat16(v.w);
    __nv_bfloat16 l0 = __float2bfloat16(v.x - __bfloat162float(h0));
    __nv_bfloat16 l1 = __float2bfloat16(v.y - __bfloat162float(h1));
    __nv_bfloat16 l2 = __float2bfloat16(v.z - __bfloat162float(h2));
    __nv_bfloat16 l3 = __float2bfloat16(v.w - __bfloat162float(h3));
    B4 hv, lv;
    hv.h2[0] = __nv_bfloat162(h0, h1); hv.h2[1] = __nv_bfloat162(h2, h3);
    lv.h2[0] = __nv_bfloat162(l0, l1); lv.h2[1] = __nv_bfloat162(l2, l3);
    int row = i >> 10, col = i & 1023;
    size_t base = (size_t)row * KP + col;
    *(uint2*)(out + base) = hv.u;
    if (mode == 0) {
        *(uint2*)(out + base + 1024) = hv.u;
        *(uint2*)(out + base + 2048) = lv.u;
    } else {
        *(uint2*)(out + base + 1024) = lv.u;
        *(uint2*)(out + base + 2048) = hv.u;
    }
}

__global__ __launch_bounds__(256) void split_all(
    const float* __restrict__ q, const float* __restrict__ k, const float* __restrict__ v,
    const float* __restrict__ wq, const float* __restrict__ wk,
    const float* __restrict__ wv, const float* __restrict__ wo,
    __nv_bfloat16* __restrict__ oq, __nv_bfloat16* __restrict__ ok, __nv_bfloat16* __restrict__ ov,
    __nv_bfloat16* __restrict__ owq, __nv_bfloat16* __restrict__ owk,
    __nv_bfloat16* __restrict__ owv, __nv_bfloat16* __restrict__ owo) {
    int bid = blockIdx.x;
    const float* src;
    __nv_bfloat16* dst;
    int mode, lb;
    if (bid < 12288) {
        int t = bid >> 12;
        lb = bid & 4095;
        src = (t == 0) ? q : (t == 1) ? k : v;
        dst = (t == 0) ? oq : (t == 1) ? ok : ov;
        mode = 0;
    } else {
        int t = (bid - 12288) >> 10;
        lb = (bid - 12288) & 1023;
        src = (t == 0) ? wq : (t == 1) ? wk : (t == 2) ? wv : wo;
        dst = (t == 0) ? owq : (t == 1) ? owk : (t == 2) ? owv : owo;
        mode = 1;
    }
    int i = (lb * 256 + threadIdx.x) * 4;
    split_one(src, dst, i, mode);
}

// ---------------- bf16 mma.sync GEMM: 128x128 CTA, 4x2 warps of 32x64 (R11 proven) ----------------
// 256 threads, 2 CTAs/SM, BK=32, 4-stage cp.async pipeline, register double-buffered frags.
struct Frags {
    uint32_t a[2][4];
    uint32_t b[8][2];
};

__device__ __forceinline__ void load_stage(uint32_t sm, const __nv_bfloat16* A,
                                           const __nv_bfloat16* B, int bm, int bn,
                                           int it, int tid) {
    size_t kof = (size_t)it * 32;
#pragma unroll
    for (int i = 0; i < 2; i++) {
        int c = tid + 256 * i;
        int r = c >> 2, kc = (c & 3) * 8;
        cp16(sm + (r * LDAB + kc) * 2, A + (size_t)(bm + r) * KP + kof + kc);
    }
#pragma unroll
    for (int i = 0; i < 2; i++) {
        int c = tid + 256 * i;
        int r = c >> 2, kc = (c & 3) * 8;
        cp16(sm + 10240 + (r * LDAB + kc) * 2, B + (size_t)(bn + r) * KP + kof + kc);
    }
}

__global__ __launch_bounds__(256, 2) void gemm_mma(
    const __nv_bfloat16* __restrict__ A, const __nv_bfloat16* __restrict__ W,
    const float* __restrict__ bias, float* __restrict__ C,
    __nv_bfloat16* __restrict__ Chi, __nv_bfloat16* __restrict__ Clo) {
    extern __shared__ char smem[];
    const uint32_t sb = smem_u32(smem);
    const int tid = threadIdx.x;
    const int wid = tid >> 5;
    const int l = tid & 31;
    const int warp_m = wid >> 1;   // 0..3
    const int warp_n = wid & 1;    // 0..1
    const int bm = blockIdx.y * 128;
    const int bn = blockIdx.x * 128;
    const int NIT = KP / 32;       // 96

    float acc[2][8][4];
#pragma unroll
    for (int mi = 0; mi < 2; mi++)
#pragma unroll
        for (int ni = 0; ni < 8; ni++)
#pragma unroll
            for (int r = 0; r < 4; r++) acc[mi][ni][r] = 0.0f;

    const int a_row = warp_m * 32 + (l & 15);
    const int a_ko = (l >> 4) << 3;
    const int b_row = warp_n * 64 + ((l >> 4) << 3) + (l & 7);
    const int b_ko = ((l >> 3) & 1) << 3;

    auto ldsm_frags = [&](Frags& f, uint32_t stage, int kcol) {
#pragma unroll
        for (int mi = 0; mi < 2; mi++)
            ldsm_x4(f.a[mi][0], f.a[mi][1], f.a[mi][2], f.a[mi][3],
                    stage + ((a_row + mi * 16) * LDAB + kcol + a_ko) * 2);
#pragma unroll
        for (int p = 0; p < 4; p++) {
            uint32_t r0, r1, r2, r3;
            ldsm_x4(r0, r1, r2, r3,
                    stage + 10240 + ((b_row + p * 16) * LDAB + kcol + b_ko) * 2);
            f.b[2 * p][0] = r0; f.b[2 * p][1] = r1;
            f.b[2 * p + 1][0] = r2; f.b[2 * p + 1][1] = r3;
        }
    };
    auto mma_all = [&](const Frags& f) {
#pragma unroll
        for (int mi = 0; mi < 2; mi++)
#pragma unroll
            for (int ni = 0; ni < 8; ni++)
                mma_bf16(acc[mi][ni], f.a[mi][0], f.a[mi][1], f.a[mi][2], f.a[mi][3],
                         f.b[ni][0], f.b[ni][1]);
    };

    // prologue: issue stages 0..2
#pragma unroll
    for (int s = 0; s < NSTAGE - 1; s++) {
        load_stage(sb + s * STAGE_BYTES, A, W, bm, bn, s, tid);
        CP_COMMIT();
    }
    CP_WAIT(2);   // stage 0 landed
    __syncthreads();

    Frags cur, nxt;
    ldsm_frags(cur, sb, 0);

    for (int it = 0; it < NIT; it++) {
        const uint32_t sCur = sb + (it % NSTAGE) * STAGE_BYTES;
        if (it + NSTAGE - 1 < NIT)
            load_stage(sb + ((it + NSTAGE - 1) % NSTAGE) * STAGE_BYTES, A, W, bm, bn,
                       it + NSTAGE - 1, tid);
        CP_COMMIT();

        ldsm_frags(nxt, sCur, 16);
        mma_all(cur);

        if (it + 1 < NIT) {
            CP_WAIT(2);          // stage it+1 landed (it+2, it+3 may be pending)
            __syncthreads();
            ldsm_frags(cur, sb + ((it + 1) % NSTAGE) * STAGE_BYTES, 0);
        }
        mma_all(nxt);
    }

    const int tr = l >> 2;
    const int tc = (l & 3) * 2;
#pragma unroll
    for (int mi = 0; mi < 2; mi++) {
#pragma unroll
        for (int ni = 0; ni < 8; ni++) {
            int row0 = bm + warp_m * 32 + mi * 16 + tr;
            int col = bn + warp_n * 64 + ni * 8 + tc;
            float2 v0 = make_float2(acc[mi][ni][0], acc[mi][ni][1]);
            float2 v1 = make_float2(acc[mi][ni][2], acc[mi][ni][3]);
            if (bias) {
                float2 bv = *(const float2*)(bias + col);
                v0.x += bv.x; v0.y += bv.y;
                v1.x += bv.x; v1.y += bv.y;
            }
            if (C) {
                *(float2*)(C + (size_t)row0 * 1024 + col) = v0;
                *(float2*)(C + (size_t)(row0 + 8) * 1024 + col) = v1;
            }
            if (Chi) {
                __nv_bfloat16 h0 = __float2bfloat16(v0.x), h1 = __float2bfloat16(v0.y);
                __nv_bfloat16 h2 = __float2bfloat16(v1.x), h3 = __float2bfloat16(v1.y);
                __nv_bfloat162 hp0(h0, h1), hp1(h2, h3);
                __nv_bfloat162 lp0(__float2bfloat16(v0.x - __bfloat162float(h0)),
                                   __float2bfloat16(v0.y - __bfloat162float(h1)));
                __nv_bfloat162 lp1(__float2bfloat16(v1.x - __bfloat162float(h2)),
                                   __float2bfloat16(v1.y - __bfloat162float(h3)));
                *(uint32_t*)(Chi + (size_t)row0 * 1024 + col) = *(uint32_t*)&hp0;
                *(uint32_t*)(Chi + (size_t)(row0 + 8) * 1024 + col) = *(uint32_t*)&hp1;
                *(uint32_t*)(Clo + (size_t)row0 * 1024 + col) = *(uint32_t*)&lp0;
                *(uint32_t*)(Clo + (size_t)(row0 + 8) * 1024 + col) = *(uint32_t*)&lp1;
            }
        }
    }
}

// ---------------- tensor-core flash attention (R11/R12 proven, fused Ac epilogue) ----------------
__global__ __launch_bounds__(128) void attn_tc(
    const __nv_bfloat16* __restrict__ Qhi, const __nv_bfloat16* __restrict__ Qlo,
    const __nv_bfloat16* __restrict__ Khi, const __nv_bfloat16* __restrict__ Klo,
    const __nv_bfloat16* __restrict__ Vhi, const __nv_bfloat16* __restrict__ Vlo,
    __nv_bfloat16* __restrict__ Ac, int S) {
    extern __shared__ char smem[];
    const uint32_t sb = smem_u32(smem);
    const int tid = threadIdx.x;
    const int w = tid >> 5;
    const int l = tid & 31;
    const int tr = l >> 2;
    const int tc = l & 3;
    const int qt = blockIdx.x, h = blockIdx.y, b = blockIdx.z;
    const int NT = S / 64;

    const uint32_t oQhi = sb;
    const uint32_t oQlo = sb + ATT_MAT_B;
    const uint32_t oSt = sb + 2 * ATT_MAT_B;

    const size_t gq = ((size_t)(b * S + qt * 64)) * D + (size_t)h * 64;

#pragma unroll
    for (int i = 0; i < 8; i++) {
        int c = tid + 128 * i;
        int mat = c >> 9, r = (c >> 3) & 63, cc = c & 7;
        const __nv_bfloat16* src = mat ? Qlo : Qhi;
        cp16((mat ? oQlo : oQhi) + (r * ATT_T + cc * 8) * 2, src + gq + (size_t)r * D + cc * 8);
    }
    auto load_kv = [&](int stage, int kt) {
        size_t gk = ((size_t)(b * S + kt * 64)) * D + (size_t)h * 64;
        const __nv_bfloat16* mats[4] = {Khi, Klo, Vhi, Vlo};
#pragma unroll
        for (int i = 0; i < 16; i++) {
            int c = tid + 128 * i;
            int mat = c >> 9, r = (c >> 3) & 63, cc = c & 7;
            cp16(oSt + stage * (4 * ATT_MAT_B) + mat * ATT_MAT_B + (r * ATT_T + cc * 8) * 2,
                 mats[mat] + gk + (size_t)r * D + cc * 8);
        }
    };
    load_kv(0, 0);
    CP_COMMIT();
    load_kv(1, 1);
    CP_COMMIT();
    CP_WAIT(1);
    __syncthreads();

    uint32_t qh[4][4], ql[4][4];
    {
        const int arow = w * 16 + (l & 15);
        const int ako = (l >> 4) << 3;
#pragma unroll
        for (int kk = 0; kk < 4; kk++) {
            ldsm_x4(qh[kk][0], qh[kk][1], qh[kk][2], qh[kk][3],
                    oQhi + (arow * ATT_T + kk * 16 + ako) * 2);
            ldsm_x4(ql[kk][0], ql[kk][1], ql[kk][2], ql[kk][3],
                    oQlo + (arow * ATT_T + kk * 16 + ako) * 2);
        }
    }

    float oacc[8][4];
#pragma unroll
    for (int ni = 0; ni < 8; ni++)
#pragma unroll
        for (int j = 0; j < 4; j++) oacc[ni][j] = 0.0f;
    float m0 = -1e30f, m1 = -1e30f, sl0 = 0.0f, sl1 = 0.0f;

    const int brow = ((l >> 4) << 3) + (l & 7);
    const int bko = ((l >> 3) & 1) << 3;
    const int vrow = (l & 7) + (((l >> 3) & 1) << 3);
    const int vcolw = (l >> 4);

    for (int kt = 0; kt < NT; kt++) {
        const uint32_t KBh = oSt + (kt & 1) * (4 * ATT_MAT_B);
        const uint32_t KBl = KBh + ATT_MAT_B;
        const uint32_t VBh = KBh + 2 * ATT_MAT_B;
        const uint32_t VBl = KBh + 3 * ATT_MAT_B;

        float sacc[8][4];
#pragma unroll
        for (int ni = 0; ni < 8; ni++)
#pragma unroll
            for (int j = 0; j < 4; j++) sacc[ni][j] = 0.0f;

#pragma unroll
        for (int kk = 0; kk < 4; kk++) {
            uint32_t bh[8][2];
#pragma unroll
            for (int np = 0; np < 4; np++) {
                uint32_t r0, r1, r2, r3;
                ldsm_x4(r0, r1, r2, r3, KBh + ((np * 16 + brow) * ATT_T + kk * 16 + bko) * 2);
                bh[2 * np][0] = r0; bh[2 * np][1] = r1;
                bh[2 * np + 1][0] = r2; bh[2 * np + 1][1] = r3;
            }
#pragma unroll
            for (int ni = 0; ni < 8; ni++)
                mma_bf16(sacc[ni], qh[kk][0], qh[kk][1], qh[kk][2], qh[kk][3], bh[ni][0], bh[ni][1]);
#pragma unroll
            for (int ni = 0; ni < 8; ni++)
                mma_bf16(sacc[ni], ql[kk][0], ql[kk][1], ql[kk][2], ql[kk][3], bh[ni][0], bh[ni][1]);
            uint32_t bl[8][2];
#pragma unroll
            for (int np = 0; np < 4; np++) {
                uint32_t r0, r1, r2, r3;
                ldsm_x4(r0, r1, r2, r3, KBl + ((np * 16 + brow) * ATT_T + kk * 16 + bko) * 2);
                bl[2 * np][0] = r0; bl[2 * np][1] = r1;
                bl[2 * np + 1][0] = r2; bl[2 * np + 1][1] = r3;
            }
#pragma unroll
            for (int ni = 0; ni < 8; ni++)
                mma_bf16(sacc[ni], qh[kk][0], qh[kk][1], qh[kk][2], qh[kk][3], bl[ni][0], bl[ni][1]);
        }

        float mx0 = -1e30f, mx1 = -1e30f;
#pragma unroll
        for (int ni = 0; ni < 8; ni++) {
            sacc[ni][0] *= 0.125f; sacc[ni][1] *= 0.125f;
            sacc[ni][2] *= 0.125f; sacc[ni][3] *= 0.125f;
            mx0 = fmaxf(mx0, fmaxf(sacc[ni][0], sacc[ni][1]));
            mx1 = fmaxf(mx1, fmaxf(sacc[ni][2], sacc[ni][3]));
        }
        mx0 = fmaxf(mx0, __shfl_xor_sync(0xffffffffu, mx0, 1));
        mx0 = fmaxf(mx0, __shfl_xor_sync(0xffffffffu, mx0, 2));
        mx1 = fmaxf(mx1, __shfl_xor_sync(0xffffffffu, mx1, 1));
        mx1 = fmaxf(mx1, __shfl_xor_sync(0xffffffffu, mx1, 2));
        float mn0 = fmaxf(m0, mx0), mn1 = fmaxf(m1, mx1);
        float c0 = __expf(m0 - mn0), c1 = __expf(m1 - mn1);
        float rs0 = 0.0f, rs1 = 0.0f;
#pragma unroll
        for (int ni = 0; ni < 8; ni++) {
            sacc[ni][0] = __expf(sacc[ni][0] - mn0);
            sacc[ni][1] = __expf(sacc[ni][1] - mn0);
            sacc[ni][2] = __expf(sacc[ni][2] - mn1);
            sacc[ni][3] = __expf(sacc[ni][3] - mn1);
            rs0 += sacc[ni][0] + sacc[ni][1];
            rs1 += sacc[ni][2] + sacc[ni][3];
        }
        rs0 += __shfl_xor_sync(0xffffffffu, rs0, 1);
        rs0 += __shfl_xor_sync(0xffffffffu, rs0, 2);
        rs1 += __shfl_xor_sync(0xffffffffu, rs1, 1);
        rs1 += __shfl_xor_sync(0xffffffffu, rs1, 2);
        sl0 = sl0 * c0 + rs0;
        sl1 = sl1 * c1 + rs1;
        m0 = mn0; m1 = mn1;
#pragma unroll
        for (int ni = 0; ni < 8; ni++) {
            oacc[ni][0] *= c0; oacc[ni][1] *= c0;
            oacc[ni][2] *= c1; oacc[ni][3] *= c1;
        }

        uint32_t ph[4][4], pl[4][4];
#pragma unroll
        for (int kk = 0; kk < 4; kk++) {
#pragma unroll
            for (int hv = 0; hv < 2; hv++) {
#pragma unroll
                for (int half = 0; half < 2; half++) {
                    float x = sacc[2 * kk + half][2 * hv + 0];
                    float y = sacc[2 * kk + half][2 * hv + 1];
                    __nv_bfloat16 hx = __float2bfloat16(x), hy = __float2bfloat16(y);
                    __nv_bfloat162 hp(hx, hy);
                    __nv_bfloat162 lp(__float2bfloat16(x - __bfloat162float(hx)),
                                      __float2bfloat16(y - __bfloat162float(hy)));
                    ph[kk][half * 2 + hv] = *(uint32_t*)&hp;
                    pl[kk][half * 2 + hv] = *(uint32_t*)&lp;
                }
            }
        }

#pragma unroll
        for (int kk = 0; kk < 4; kk++) {
            uint32_t bv[8][2];
#pragma unroll
            for (int np = 0; np < 4; np++) {
                uint32_t r0, r1, r2, r3;
                ldsm_x4_t(r0, r1, r2, r3,
                          VBh + ((kk * 16 + vrow) * ATT_T + 8 * (2 * np + vcolw)) * 2);
                bv[2 * np][0] = r0; bv[2 * np][1] = r1;
                bv[2 * np + 1][0] = r2; bv[2 * np + 1][1] = r3;
            }
#pragma unroll
            for (int ni = 0; ni < 8; ni++)
                mma_bf16(oacc[ni], ph[kk][0], ph[kk][1], ph[kk][2], ph[kk][3], bv[ni][0], bv[ni][1]);
#pragma unroll
            for (int ni = 0; ni < 8; ni++)
                mma_bf16(oacc[ni], pl[kk][0], pl[kk][1], pl[kk][2], pl[kk][3], bv[ni][0], bv[ni][1]);
            uint32_t bvl[8][2];
#pragma unroll
            for (int np = 0; np < 4; np++) {
                uint32_t r0, r1, r2, r3;
                ldsm_x4_t(r0, r1, r2, r3,
                          VBl + ((kk * 16 + vrow) * ATT_T + 8 * (2 * np + vcolw)) * 2);
                bvl[2 * np][0] = r0; bvl[2 * np][1] = r1;
                bvl[2 * np + 1][0] = r2; bvl[2 * np + 1][1] = r3;
            }
#pragma unroll
            for (int ni = 0; ni < 8; ni++)
                mma_bf16(oacc[ni], ph[kk][0], ph[kk][1], ph[kk][2], ph[kk][3], bvl[ni][0], bvl[ni][1]);
        }

        __syncthreads();
        if (kt + 2 < NT) {
            load_kv(kt & 1, kt + 2);
            CP_COMMIT();
            CP_WAIT(1);
            __syncthreads();
        } else if (kt + 1 < NT) {
            CP_WAIT(0);
            __syncthreads();
        }
    }

    // ---- epilogue: write Ac hi/lo in split-K' mode-0 layout directly ----
    float i0 = 1.0f / sl0, i1 = 1.0f / sl1;
    const int qrow = qt * 64 + w * 16;
    auto store_pair = [&](int grow, int col, float x, float y) {
        __nv_bfloat16 hx = __float2bfloat16(x), hy = __float2bfloat16(y);
        __nv_bfloat162 hp(hx, hy);
        __nv_bfloat162 lp(__float2bfloat16(x - __bfloat162float(hx)),
                          __float2bfloat16(y - __bfloat162float(hy)));
        size_t base = (size_t)grow * KP + col;
        *(uint32_t*)(Ac + base) = *(uint32_t*)&hp;
        *(uint32_t*)(Ac + base + 1024) = *(uint32_t*)&hp;
        *(uint32_t*)(Ac + base + 2048) = *(uint32_t*)&lp;
    };
#pragma unroll
    for (int ni = 0; ni < 8; ni++) {
        int grow = b * S + qrow + tr;
        int col = h * 64 + ni * 8 + tc * 2;
        store_pair(grow, col, oacc[ni][0] * i0, oacc[ni][1] * i0);
        store_pair(grow + 8, col, oacc[ni][2] * i1, oacc[ni][3] * i1);
    }
}

// ---------------- launch ----------------
extern "C" void kernel_launch(void* const* d_in, const int* in_sizes, int n_in,
                              void* d_out, int out_size) {
    const float* key = (const float*)d_in[0];
    const float* query = (const float*)d_in[1];
    const float* value = (const float*)d_in[2];
    const float* Wq = (const float*)d_in[3];
    const float* Wk = (const float*)d_in[4];
    const float* Wv = (const float*)d_in[5];
    const float* Wo = (const float*)d_in[6];
    const float* bo = (const float*)d_in[7];

    const int B = 2;
    const int S = in_sizes[0] / (B * D);  // 2048
    const int M = B * S;                  // 4096

    __nv_bfloat16 *Aq, *Ak, *Av, *Ac, *Wq2, *Wk2, *Wv2, *Wo2;
    __nv_bfloat16 *Qh, *Ql, *Kh, *Kl, *Vh, *Vl;
    cudaGetSymbolAddress((void**)&Aq, g_Aq);
    cudaGetSymbolAddress((void**)&Ak, g_Ak);
    cudaGetSymbolAddress((void**)&Av, g_Av);
    cudaGetSymbolAddress((void**)&Ac, g_Ac);
    cudaGetSymbolAddress((void**)&Wq2, g_Wq2);
    cudaGetSymbolAddress((void**)&Wk2, g_Wk2);
    cudaGetSymbolAddress((void**)&Wv2, g_Wv2);
    cudaGetSymbolAddress((void**)&Wo2, g_Wo2);
    cudaGetSymbolAddress((void**)&Qh, g_Qhi);
    cudaGetSymbolAddress((void**)&Ql, g_Qlo);
    cudaGetSymbolAddress((void**)&Kh, g_Khi);
    cudaGetSymbolAddress((void**)&Kl, g_Klo);
    cudaGetSymbolAddress((void**)&Vh, g_Vhi);
    cudaGetSymbolAddress((void**)&Vl, g_Vlo);

    cudaFuncSetAttribute(gemm_mma, cudaFuncAttributeMaxDynamicSharedMemorySize, GSMEM);
    cudaFuncSetAttribute(attn_tc, cudaFuncAttributeMaxDynamicSharedMemorySize, ATT_SMEM);

    dim3 gG(D / 128, M / 128);  // (8, 32)

    split_all<<<16384, 256>>>(query, key, value, Wq, Wk, Wv, Wo,
                              Aq, Ak, Av, Wq2, Wk2, Wv2, Wo2);
    gemm_mma<<<gG, 256, GSMEM>>>(Aq, Wq2, nullptr, nullptr, Qh, Ql);
    gemm_mma<<<gG, 256, GSMEM>>>(Ak, Wk2, nullptr, nullptr, Kh, Kl);
    gemm_mma<<<gG, 256, GSMEM>>>(Av, Wv2, nullptr, nullptr, Vh, Vl);

    dim3 gAt(S / 64, HEADS, B);  // (32, 16, 2)
    attn_tc<<<gAt, 128, ATT_SMEM>>>(Qh, Ql, Kh, Kl, Vh, Vl, Ac, S);

    gemm_mma<<<gG, 256, GSMEM>>>(Ac, Wo2, bo, (float*)d_out, nullptr, nullptr);
}